// round 14
// baseline (speedup 1.0000x reference)
#include <cuda_runtime.h>
#include <cuda_bf16.h>
#include <cuda_fp16.h>
#include <cstdint>
#include <cmath>

// Problem constants (fixed by the dataset)
#define NN      50000
#define F_IN    512
#define HID     128
#define H1      4
#define D1      (H1 * HID)     // 512
#define E_MAX   1000000
#define NEG_SLOPE 0.2f
#define NBLK    ((NN + 255) / 256)   // 196 scan blocks

// ---------------- scratch (device globals; no allocation allowed) -------------
__device__ __half g_xh[(size_t)NN * F_IN];    // x (fp16)          [N, 512]
__device__ __half g_w1t[(size_t)D1 * F_IN];   // W1^T (fp16)       [512, 512]
__device__ __half g_w2t[(size_t)HID * D1];    // W2^T (fp16)       [128, 512]
__device__ __half g_h1h[(size_t)NN * D1];     // x @ W1  (fp16)    [N, 512]
__device__ __half g_agg1h[(size_t)NN * D1];   // ELU(GAT1) (fp16)  [N, 512]
__device__ __half g_h2h[(size_t)NN * HID];    // agg1 @ W2 (fp16)  [N, 128]
__device__ float g_as1[NN * H1];
__device__ float g_ad1[NN * H1];
__device__ float g_as2[NN];
__device__ float g_ad2[NN];
__device__ int   g_count[NN];
__device__ int   g_rowptr[NN + 1];
__device__ int   g_woff[NN];
__device__ int   g_bsum[256];
__device__ int   g_boff[256];
__device__ int   g_srcs[E_MAX];               // edge srcs sorted by dst (CSR)

// ---------------- input conversion -------------------------------------------
__global__ void cvt_x_kernel(const float* __restrict__ x) {
    size_t tot = (size_t)NN * F_IN / 4;
    for (size_t i = blockIdx.x * blockDim.x + threadIdx.x; i < tot;
         i += (size_t)gridDim.x * blockDim.x) {
        float4 v = *(const float4*)&x[i * 4];
        __half2 lo = __float22half2_rn(make_float2(v.x, v.y));
        __half2 hi = __float22half2_rn(make_float2(v.z, v.w));
        *(uint2*)&g_xh[i * 4] = make_uint2(*(uint32_t*)&lo, *(uint32_t*)&hi);
    }
}

// transpose + convert weights: W[K][Nc] -> Wt[Nc][K] fp16
__global__ void cvt_w_kernel(const float* __restrict__ W1,
                             const float* __restrict__ W2) {
    int tot1 = F_IN * D1;
    int tot2 = D1 * HID;
    for (int i = blockIdx.x * blockDim.x + threadIdx.x; i < tot1 + tot2;
         i += gridDim.x * blockDim.x) {
        if (i < tot1) {
            int k = i / D1, n = i % D1;
            g_w1t[(size_t)n * F_IN + k] = __float2half_rn(W1[i]);
        } else {
            int j = i - tot1;
            int k = j / HID, n = j % HID;
            g_w2t[(size_t)n * D1 + k] = __float2half_rn(W2[j]);
        }
    }
}

// ---------------- CSR build ---------------------------------------------------
__global__ void count_kernel(const int* __restrict__ ei, int E) {
    int tot = E + NN;
    for (int i = blockIdx.x * blockDim.x + threadIdx.x; i < tot;
         i += gridDim.x * blockDim.x) {
        int dst = (i < E) ? ei[E + i] : (i - E);
        atomicAdd(&g_count[dst], 1);
    }
}

__global__ void scan1_kernel() {
    __shared__ int sh[256];
    int tid = threadIdx.x;
    int i = blockIdx.x * 256 + tid;
    int v = (i < NN) ? g_count[i] : 0;
    sh[tid] = v;
    __syncthreads();
#pragma unroll
    for (int s = 1; s < 256; s <<= 1) {
        int t = (tid >= s) ? sh[tid - s] : 0;
        __syncthreads();
        sh[tid] += t;
        __syncthreads();
    }
    if (i < NN) g_rowptr[i] = sh[tid] - v;   // block-local exclusive
    if (tid == 255) g_bsum[blockIdx.x] = sh[255];
}

__global__ void scan2_kernel() {
    __shared__ int sh[256];
    int tid = threadIdx.x;
    int v = (tid < NBLK) ? g_bsum[tid] : 0;
    sh[tid] = v;
    __syncthreads();
#pragma unroll
    for (int s = 1; s < 256; s <<= 1) {
        int t = (tid >= s) ? sh[tid - s] : 0;
        __syncthreads();
        sh[tid] += t;
        __syncthreads();
    }
    if (tid < NBLK) g_boff[tid] = sh[tid] - v;
    if (tid == 255) g_rowptr[NN] = sh[255];
}

__global__ void scan3_kernel() {
    int i = blockIdx.x * 256 + threadIdx.x;
    if (i < NN) {
        int v = g_rowptr[i] + g_boff[blockIdx.x];
        g_rowptr[i] = v;
        g_woff[i]   = v;
    }
}

__global__ void fill_kernel(const int* __restrict__ ei, int E) {
    int tot = E + NN;
    for (int i = blockIdx.x * blockDim.x + threadIdx.x; i < tot;
         i += gridDim.x * blockDim.x) {
        int src, dst;
        if (i < E) { src = ei[i]; dst = ei[E + i]; }
        else       { src = dst = i - E; }
        int pos = atomicAdd(&g_woff[dst], 1);
        g_srcs[pos] = src;
    }
}

// ---------------- fp16 tensor-core GEMM + fused alpha epilogue ----------------
// C[M,Nc] = A[M,K] @ Bt[Nc,K]^T (fp16 out). BM=128, BN=128, BK=64 halves,
// 3-stage cp.async pipeline, 256 threads (8 warps 4x2), warp tile 32x64.
// nc_off shifts the column window (head-sliced launches). Also accumulates
// as[row] += sum_col C[row,col]*a_src[col] (and a_dst) via quad shfl +
// atomicAdd; head (bn>>7) is uniform per CTA.
#define BKH 64
#define HS  72
#define NSTAGE 3
#define GEMM_SMEM (size_t)((NSTAGE * 128 * HS + NSTAGE * 128 * HS) * 2)

__device__ __forceinline__ void cp_async16(void* smem, const void* gptr, bool pred) {
    uint32_t saddr = (uint32_t)__cvta_generic_to_shared(smem);
    int bytes = pred ? 16 : 0;
    asm volatile("cp.async.cg.shared.global [%0], [%1], 16, %2;\n"
                 :: "r"(saddr), "l"(gptr), "r"(bytes));
}

__global__ __launch_bounds__(256, 2)
void gemm_f16_kernel(const __half* __restrict__ A, const __half* __restrict__ Bt,
                     __half* __restrict__ C, int M, int K, int Nc, int nc_off,
                     const float* __restrict__ av_src,
                     const float* __restrict__ av_dst,
                     float* __restrict__ as_out, float* __restrict__ ad_out,
                     int astride) {
    extern __shared__ __half smp[];
    __half (*As)[128][HS] = (__half (*)[128][HS])smp;
    __half (*Bs)[128][HS] = (__half (*)[128][HS])(smp + NSTAGE * 128 * HS);

    int tid  = threadIdx.x;
    int warp = tid >> 5;
    int lane = tid & 31;
    int wm = (warp >> 1) * 32;       // 4 row groups
    int wn = (warp & 1) * 64;        // 2 col groups of 64
    int g  = lane >> 2;
    int t  = lane & 3;
    int bm = blockIdx.y * 128;
    int bn = blockIdx.x * 128 + nc_off;
    int ahead = bn >> 7;             // head index (uniform per CTA)

    float acc[2][8][4];
#pragma unroll
    for (int mt = 0; mt < 2; mt++)
#pragma unroll
        for (int nt = 0; nt < 8; nt++)
#pragma unroll
            for (int r = 0; r < 4; r++) acc[mt][nt][r] = 0.f;

    const int cRow = tid >> 3;       // 0..31
    const int cC   = tid & 7;        // 16B chunk (8 halves)

    auto issue_tile = [&](int k0, int buf) {
#pragma unroll
        for (int i = 0; i < 4; i++) {
            int row = cRow + 32 * i;
            int gr  = bm + row;
            cp_async16(&As[buf][row][cC * 8],
                       &A[(size_t)gr * K + k0 + cC * 8], gr < M);
        }
#pragma unroll
        for (int i = 0; i < 4; i++) {
            int row = cRow + 32 * i;
            cp_async16(&Bs[buf][row][cC * 8],
                       &Bt[(size_t)(bn + row) * K + k0 + cC * 8], true);
        }
        asm volatile("cp.async.commit_group;");
    };

    int NT = K / BKH;
    issue_tile(0, 0);
    if (NT > 1) issue_tile(BKH, 1);

    for (int it = 0; it < NT; it++) {
        int cur = it % NSTAGE;
        if (it + 2 < NT) {
            issue_tile((it + 2) * BKH, (it + 2) % NSTAGE);
            asm volatile("cp.async.wait_group 2;");
        } else if (it + 1 < NT) {
            asm volatile("cp.async.wait_group 1;");
        } else {
            asm volatile("cp.async.wait_group 0;");
        }
        __syncthreads();

#pragma unroll
        for (int ks = 0; ks < 4; ks++) {
            int kb = ks * 16;
            uint32_t a[2][4];
#pragma unroll
            for (int mt = 0; mt < 2; mt++) {
                int r0 = wm + mt * 16;
                a[mt][0] = *(uint32_t*)&As[cur][r0 + g][kb + 2 * t];
                a[mt][1] = *(uint32_t*)&As[cur][r0 + g + 8][kb + 2 * t];
                a[mt][2] = *(uint32_t*)&As[cur][r0 + g][kb + 2 * t + 8];
                a[mt][3] = *(uint32_t*)&As[cur][r0 + g + 8][kb + 2 * t + 8];
            }
#pragma unroll
            for (int nt = 0; nt < 8; nt++) {
                int c0 = wn + nt * 8;
                uint32_t b0 = *(uint32_t*)&Bs[cur][c0 + g][kb + 2 * t];
                uint32_t b1 = *(uint32_t*)&Bs[cur][c0 + g][kb + 2 * t + 8];
#pragma unroll
                for (int mt = 0; mt < 2; mt++) {
                    asm volatile(
                        "mma.sync.aligned.m16n8k16.row.col.f32.f16.f16.f32 "
                        "{%0,%1,%2,%3}, {%4,%5,%6,%7}, {%8,%9}, {%0,%1,%2,%3};"
                        : "+f"(acc[mt][nt][0]), "+f"(acc[mt][nt][1]),
                          "+f"(acc[mt][nt][2]), "+f"(acc[mt][nt][3])
                        : "r"(a[mt][0]), "r"(a[mt][1]), "r"(a[mt][2]), "r"(a[mt][3]),
                          "r"(b0), "r"(b1));
                }
            }
        }
        __syncthreads();
    }

    // ---- C store + fused alpha partial dots ----
#pragma unroll
    for (int mt = 0; mt < 2; mt++) {
        int r0 = bm + wm + mt * 16 + g;
        int r1 = r0 + 8;
        float s0 = 0.f, d0 = 0.f, s1 = 0.f, d1 = 0.f;
#pragma unroll
        for (int nt = 0; nt < 8; nt++) {
            int col = bn + wn + nt * 8 + t * 2;
            if (r0 < M)
                *(__half2*)&C[(size_t)r0 * Nc + col] =
                    __float22half2_rn(make_float2(acc[mt][nt][0], acc[mt][nt][1]));
            if (r1 < M)
                *(__half2*)&C[(size_t)r1 * Nc + col] =
                    __float22half2_rn(make_float2(acc[mt][nt][2], acc[mt][nt][3]));
            float a0 = av_src[col], a1 = av_src[col + 1];
            float e0 = av_dst[col], e1 = av_dst[col + 1];
            s0 = fmaf(acc[mt][nt][0], a0, fmaf(acc[mt][nt][1], a1, s0));
            d0 = fmaf(acc[mt][nt][0], e0, fmaf(acc[mt][nt][1], e1, d0));
            s1 = fmaf(acc[mt][nt][2], a0, fmaf(acc[mt][nt][3], a1, s1));
            d1 = fmaf(acc[mt][nt][2], e0, fmaf(acc[mt][nt][3], e1, d1));
        }
        // reduce over the quad (t = 0..3, same g)
#pragma unroll
        for (int o = 1; o < 4; o <<= 1) {
            s0 += __shfl_xor_sync(0xffffffffu, s0, o);
            d0 += __shfl_xor_sync(0xffffffffu, d0, o);
            s1 += __shfl_xor_sync(0xffffffffu, s1, o);
            d1 += __shfl_xor_sync(0xffffffffu, d1, o);
        }
        if (t == 0) {
            if (r0 < M) {
                atomicAdd(&as_out[r0 * astride + ahead], s0);
                atomicAdd(&ad_out[r0 * astride + ahead], d0);
            }
            if (r1 < M) {
                atomicAdd(&as_out[r1 * astride + ahead], s1);
                atomicAdd(&ad_out[r1 * astride + ahead], d1);
            }
        }
    }
}

__device__ __forceinline__ float lrelu(float x) {
    return x >= 0.f ? x : NEG_SLOPE * x;
}

// ---------------- fused softmax + aggregate (layer1, 2-head slice) ------------
// Single pass, no max subtraction (logits ~N(0,2): exp safely in fp32 range).
// Block = 2 nodes x 2 heads (128 threads); hb = head base of the slice.
__global__ void agg1_kernel(const float* __restrict__ b1, int hb) {
    int n = blockIdx.x * 2 + (threadIdx.x >> 6);
    int w = hb + ((threadIdx.x >> 5) & 1);
    int lane = threadIdx.x & 31;
    int start = g_rowptr[n];
    int end   = g_rowptr[n + 1];
    float adv = g_ad1[n * H1 + w];

    float4 acc = make_float4(0.f, 0.f, 0.f, 0.f);
    float ssum = 0.f;
    int i = start;
    for (; i + 4 <= end; i += 4) {
        int s0 = g_srcs[i],     s1 = g_srcs[i + 1];
        int s2 = g_srcs[i + 2], s3 = g_srcs[i + 3];
        uint2 q0 = *(const uint2*)&g_h1h[(size_t)s0 * D1 + w * HID + lane * 4];
        uint2 q1 = *(const uint2*)&g_h1h[(size_t)s1 * D1 + w * HID + lane * 4];
        uint2 q2 = *(const uint2*)&g_h1h[(size_t)s2 * D1 + w * HID + lane * 4];
        uint2 q3 = *(const uint2*)&g_h1h[(size_t)s3 * D1 + w * HID + lane * 4];
        float p0 = __expf(lrelu(g_as1[s0 * H1 + w] + adv));
        float p1 = __expf(lrelu(g_as1[s1 * H1 + w] + adv));
        float p2 = __expf(lrelu(g_as1[s2 * H1 + w] + adv));
        float p3 = __expf(lrelu(g_as1[s3 * H1 + w] + adv));
        ssum += (p0 + p1) + (p2 + p3);
        float2 v0a = __half22float2(*(__half2*)&q0.x);
        float2 v0b = __half22float2(*(__half2*)&q0.y);
        float2 v1a = __half22float2(*(__half2*)&q1.x);
        float2 v1b = __half22float2(*(__half2*)&q1.y);
        float2 v2a = __half22float2(*(__half2*)&q2.x);
        float2 v2b = __half22float2(*(__half2*)&q2.y);
        float2 v3a = __half22float2(*(__half2*)&q3.x);
        float2 v3b = __half22float2(*(__half2*)&q3.y);
        acc.x = fmaf(p0, v0a.x, fmaf(p1, v1a.x, fmaf(p2, v2a.x, fmaf(p3, v3a.x, acc.x))));
        acc.y = fmaf(p0, v0a.y, fmaf(p1, v1a.y, fmaf(p2, v2a.y, fmaf(p3, v3a.y, acc.y))));
        acc.z = fmaf(p0, v0b.x, fmaf(p1, v1b.x, fmaf(p2, v2b.x, fmaf(p3, v3b.x, acc.z))));
        acc.w = fmaf(p0, v0b.y, fmaf(p1, v1b.y, fmaf(p2, v2b.y, fmaf(p3, v3b.y, acc.w))));
    }
    for (; i < end; i++) {
        int s0 = g_srcs[i];
        uint2 q0 = *(const uint2*)&g_h1h[(size_t)s0 * D1 + w * HID + lane * 4];
        float p0 = __expf(lrelu(g_as1[s0 * H1 + w] + adv));
        ssum += p0;
        float2 v0a = __half22float2(*(__half2*)&q0.x);
        float2 v0b = __half22float2(*(__half2*)&q0.y);
        acc.x = fmaf(p0, v0a.x, acc.x);
        acc.y = fmaf(p0, v0a.y, acc.y);
        acc.z = fmaf(p0, v0b.x, acc.z);
        acc.w = fmaf(p0, v0b.y, acc.w);
    }
    float inv = 1.f / (ssum + 1e-16f);
    float4 bb = *(const float4*)&b1[w * HID + lane * 4];
    float4 o;
    o.x = acc.x * inv + bb.x;
    o.y = acc.y * inv + bb.y;
    o.z = acc.z * inv + bb.z;
    o.w = acc.w * inv + bb.w;
    o.x = o.x > 0.f ? o.x : expm1f(o.x);
    o.y = o.y > 0.f ? o.y : expm1f(o.y);
    o.z = o.z > 0.f ? o.z : expm1f(o.z);
    o.w = o.w > 0.f ? o.w : expm1f(o.w);
    __half2 lo = __float22half2_rn(make_float2(o.x, o.y));
    __half2 hi = __float22half2_rn(make_float2(o.z, o.w));
    *(uint2*)&g_agg1h[(size_t)n * D1 + w * HID + lane * 4] =
        make_uint2(*(uint32_t*)&lo, *(uint32_t*)&hi);
}

// ---------------- fused softmax + aggregate (layer2, H=1) ---------------------
__global__ void agg2_kernel(const float* __restrict__ b2, float* __restrict__ out) {
    int n = (blockIdx.x * blockDim.x + threadIdx.x) >> 5;
    int lane = threadIdx.x & 31;
    if (n >= NN) return;
    int start = g_rowptr[n];
    int end   = g_rowptr[n + 1];
    float adv = g_ad2[n];

    float4 acc = make_float4(0.f, 0.f, 0.f, 0.f);
    float ssum = 0.f;
    int i = start;
    for (; i + 4 <= end; i += 4) {
        int s0 = g_srcs[i],     s1 = g_srcs[i + 1];
        int s2 = g_srcs[i + 2], s3 = g_srcs[i + 3];
        uint2 q0 = *(const uint2*)&g_h2h[(size_t)s0 * HID + lane * 4];
        uint2 q1 = *(const uint2*)&g_h2h[(size_t)s1 * HID + lane * 4];
        uint2 q2 = *(const uint2*)&g_h2h[(size_t)s2 * HID + lane * 4];
        uint2 q3 = *(const uint2*)&g_h2h[(size_t)s3 * HID + lane * 4];
        float p0 = __expf(lrelu(g_as2[s0] + adv));
        float p1 = __expf(lrelu(g_as2[s1] + adv));
        float p2 = __expf(lrelu(g_as2[s2] + adv));
        float p3 = __expf(lrelu(g_as2[s3] + adv));
        ssum += (p0 + p1) + (p2 + p3);
        float2 v0a = __half22float2(*(__half2*)&q0.x);
        float2 v0b = __half22float2(*(__half2*)&q0.y);
        float2 v1a = __half22float2(*(__half2*)&q1.x);
        float2 v1b = __half22float2(*(__half2*)&q1.y);
        float2 v2a = __half22float2(*(__half2*)&q2.x);
        float2 v2b = __half22float2(*(__half2*)&q2.y);
        float2 v3a = __half22float2(*(__half2*)&q3.x);
        float2 v3b = __half22float2(*(__half2*)&q3.y);
        acc.x = fmaf(p0, v0a.x, fmaf(p1, v1a.x, fmaf(p2, v2a.x, fmaf(p3, v3a.x, acc.x))));
        acc.y = fmaf(p0, v0a.y, fmaf(p1, v1a.y, fmaf(p2, v2a.y, fmaf(p3, v3a.y, acc.y))));
        acc.z = fmaf(p0, v0b.x, fmaf(p1, v1b.x, fmaf(p2, v2b.x, fmaf(p3, v3b.x, acc.z))));
        acc.w = fmaf(p0, v0b.y, fmaf(p1, v1b.y, fmaf(p2, v2b.y, fmaf(p3, v3b.y, acc.w))));
    }
    for (; i < end; i++) {
        int s0 = g_srcs[i];
        uint2 q0 = *(const uint2*)&g_h2h[(size_t)s0 * HID + lane * 4];
        float p0 = __expf(lrelu(g_as2[s0] + adv));
        ssum += p0;
        float2 v0a = __half22float2(*(__half2*)&q0.x);
        float2 v0b = __half22float2(*(__half2*)&q0.y);
        acc.x = fmaf(p0, v0a.x, acc.x);
        acc.y = fmaf(p0, v0a.y, acc.y);
        acc.z = fmaf(p0, v0b.x, acc.z);
        acc.w = fmaf(p0, v0b.y, acc.w);
    }
    float inv = 1.f / (ssum + 1e-16f);
    float4 bb = *(const float4*)&b2[lane * 4];
    float4 o;
    o.x = acc.x * inv + bb.x;
    o.y = acc.y * inv + bb.y;
    o.z = acc.z * inv + bb.z;
    o.w = acc.w * inv + bb.w;
    *(float4*)&out[(size_t)n * HID + lane * 4] = o;
}

// ---------------- launch ------------------------------------------------------
extern "C" void kernel_launch(void* const* d_in, const int* in_sizes, int n_in,
                              void* d_out, int out_size) {
    const float* x      = (const float*)d_in[0];
    const int*   ei     = (const int*)  d_in[1];
    const float* W1     = (const float*)d_in[2];
    const float* a_src1 = (const float*)d_in[3];
    const float* a_dst1 = (const float*)d_in[4];
    const float* b1     = (const float*)d_in[5];
    const float* W2     = (const float*)d_in[6];
    const float* a_src2 = (const float*)d_in[7];
    const float* a_dst2 = (const float*)d_in[8];
    const float* b2     = (const float*)d_in[9];
    float*       out    = (float*)d_out;

    int E = in_sizes[1] / 2;

    __half *xhp, *w1tp, *w2tp, *h1p, *agg1p, *h2p;
    int *countp;
    float *as1p, *ad1p, *as2p, *ad2p;
    cudaGetSymbolAddress((void**)&xhp,   g_xh);
    cudaGetSymbolAddress((void**)&w1tp,  g_w1t);
    cudaGetSymbolAddress((void**)&w2tp,  g_w2t);
    cudaGetSymbolAddress((void**)&h1p,   g_h1h);
    cudaGetSymbolAddress((void**)&agg1p, g_agg1h);
    cudaGetSymbolAddress((void**)&h2p,   g_h2h);
    cudaGetSymbolAddress((void**)&countp, g_count);
    cudaGetSymbolAddress((void**)&as1p,  g_as1);
    cudaGetSymbolAddress((void**)&ad1p,  g_ad1);
    cudaGetSymbolAddress((void**)&as2p,  g_as2);
    cudaGetSymbolAddress((void**)&ad2p,  g_ad2);

    cudaFuncSetAttribute(gemm_f16_kernel,
                         cudaFuncAttributeMaxDynamicSharedMemorySize,
                         (int)GEMM_SMEM);

    // persistent side stream + events (created once; structure-only)
    static cudaStream_t s2 = nullptr;
    static cudaEvent_t ev_fork = nullptr, ev_a = nullptr, ev_b = nullptr,
                       ev_aggdone = nullptr;
    if (!s2) {
        cudaStreamCreateWithFlags(&s2, cudaStreamNonBlocking);
        cudaEventCreateWithFlags(&ev_fork, cudaEventDisableTiming);
        cudaEventCreateWithFlags(&ev_a, cudaEventDisableTiming);
        cudaEventCreateWithFlags(&ev_b, cudaEventDisableTiming);
        cudaEventCreateWithFlags(&ev_aggdone, cudaEventDisableTiming);
    }

    // ---- zero alpha accumulators used by GEMM1 epilogue ----
    cudaMemsetAsync(as1p, 0, NN * H1 * sizeof(float), 0);
    cudaMemsetAsync(ad1p, 0, NN * H1 * sizeof(float), 0);

    // ---- fork: CSR build + as2/ad2 memsets on s2 ----
    cudaEventRecord(ev_fork, 0);
    cudaStreamWaitEvent(s2, ev_fork, 0);

    cudaMemsetAsync(countp, 0, NN * sizeof(int), s2);
    cudaMemsetAsync(as2p, 0, NN * sizeof(float), s2);
    cudaMemsetAsync(ad2p, 0, NN * sizeof(float), s2);
    count_kernel<<<3336, 256, 0, s2>>>(ei, E);
    scan1_kernel<<<NBLK, 256, 0, s2>>>();
    scan2_kernel<<<1, 256, 0, s2>>>();
    scan3_kernel<<<NBLK, 256, 0, s2>>>();
    fill_kernel<<<3336, 256, 0, s2>>>(ei, E);

    // ---- main chain: cvt -> GEMM1 slice A (heads 0-1) -> slice B (heads 2-3)
    cvt_x_kernel<<<3336, 256>>>(x);
    cvt_w_kernel<<<1312, 256>>>(W1, W2);
    gemm_f16_kernel<<<dim3(2, (NN + 127) / 128), 256, GEMM_SMEM>>>(
        xhp, w1tp, h1p, NN, F_IN, D1, 0, a_src1, a_dst1, as1p, ad1p, H1);
    cudaEventRecord(ev_a, 0);
    gemm_f16_kernel<<<dim3(2, (NN + 127) / 128), 256, GEMM_SMEM>>>(
        xhp, w1tp, h1p, NN, F_IN, D1, 256, a_src1, a_dst1, as1p, ad1p, H1);
    cudaEventRecord(ev_b, 0);

    // ---- s2: agg1 heads 0-1 overlaps GEMM1 slice B ----
    cudaStreamWaitEvent(s2, ev_a, 0);
    agg1_kernel<<<NN / 2, 128, 0, s2>>>(b1, 0);
    cudaStreamWaitEvent(s2, ev_b, 0);
    agg1_kernel<<<NN / 2, 128, 0, s2>>>(b1, 2);
    cudaEventRecord(ev_aggdone, s2);

    // ---- main: layer 2 after aggregation complete ----
    cudaStreamWaitEvent(0, ev_aggdone, 0);
    gemm_f16_kernel<<<dim3(1, (NN + 127) / 128), 256, GEMM_SMEM>>>(
        agg1p, w2tp, h2p, NN, D1, HID, 0, a_src2, a_dst2, as2p, ad2p, 1);
    agg2_kernel<<<(NN * 32 + 255) / 256, 256>>>(b2, out);
}